// round 17
// baseline (speedup 1.0000x reference)
#include <cuda_runtime.h>
#include <cstdint>
#include <cstddef>
#include <cuda_fp16.h>

#define GRIDB 288
#define NTHR  256
#define Bsz   128
#define Tlen  512
#define Vocab 512
#define Emb   512
#define Hid   1024
#define G4    4096

// planar fp16-pair images: per k-tile = plane0 (128x16 u16 s0) + plane1 (s1), 8KB
#define KTU    2048                  // u32 per k-tile image (2 planes x 1024)
#define NSTG   4                     // cp.async pipeline stages
#define STG_U  (2 * KTU)             // A img + W img per stage (u32)
#define SMEM_DYN (NSTG * STG_U * 4)  // 65536 bytes

#define LCH    8                     // logits partial chunks
// partial chunk buffers: [0..5]=Whh0(6), [6..11]=Wih1(6), [12..16]=Whh1(5)
#define NPART  17

// ---------------- device scratch (static; no runtime allocation) ----------------
__device__ uint32_t g_Wih0s[(size_t)32 * 32 * KTU];   // setup only
__device__ uint32_t g_Whh0s[(size_t)32 * 64 * KTU];
__device__ uint32_t g_Wih1s[(size_t)32 * 64 * KTU];
__device__ uint32_t g_Whh1s[(size_t)32 * 64 * KTU];
__device__ uint32_t g_fcws [(size_t)4  * 64 * KTU];
__device__ uint32_t g_Ei  [(size_t)4  * 32 * KTU];    // emb image (setup only)
__device__ uint32_t g_H0i[(size_t)64 * KTU];
__device__ uint32_t g_H1i[(size_t)64 * KTU];

__device__ float g_EW0[(size_t)Vocab * G4];           // emb @ Wih0^T  (8MB)
__device__ float g_C0[Bsz * Hid];
__device__ float g_C1[Bsz * Hid];
__device__ float g_part[(size_t)NPART * Bsz * G4];    // partial chunk buffers
__device__ float g_lpart[LCH * Bsz * Vocab];          // logits partials
__device__ float g_bias0[G4];
__device__ float g_bias1[G4];
__device__ int   g_tok[Bsz];
__device__ unsigned char g_dec[Tlen * Bsz];

// ---------------- software grid barrier (generation-continued) ----------------
__device__ unsigned long long g_cnt;
__device__ volatile unsigned long long g_gen;

__device__ __forceinline__ void grid_sync(unsigned long long& lgen) {
    __threadfence();
    __syncthreads();
    if (threadIdx.x == 0) {
        lgen += 1ULL;
        unsigned long long a = atomicAdd(&g_cnt, 1ULL) + 1ULL;
        if (a == lgen * (unsigned long long)GRIDB) {
            g_gen = lgen;
            __threadfence();
        } else {
            while (g_gen < lgen) { __nanosleep(16); }
            __threadfence();
        }
    }
    __syncthreads();
}

// ---------------- small helpers ----------------
__device__ __forceinline__ unsigned rotl32(unsigned x, int d) {
    return (x << d) | (x >> (32 - d));
}
__device__ __forceinline__ unsigned short h0u(float v) {
    return __half_as_ushort(__float2half_rn(v));
}
__device__ __forceinline__ unsigned short h1u(float v) {
    float r = v - __half2float(__float2half_rn(v));
    return __half_as_ushort(__float2half_rn(r));
}

__device__ __forceinline__ float rcpa(float x) {
    float r;
    asm("rcp.approx.f32 %0, %1;" : "=f"(r) : "f"(x));
    return r;
}
// batched reciprocal: 1 MUFU.RCP for 4 values (Montgomery inversion)
__device__ __forceinline__ void rcp4(float a, float b, float c, float d,
                                     float& ra, float& rb, float& rc, float& rd) {
    float p2 = a * b, p3 = p2 * c, p4 = p3 * d;
    float r4 = rcpa(p4);
    rd = r4 * p3;
    float r3 = r4 * d;
    rc = r3 * p2;
    float r2 = r3 * c;
    rb = r2 * a;
    ra = r2 * b;
}
__device__ __forceinline__ float cl16(float x) { return fminf(fmaxf(x, -16.f), 16.f); }
__device__ __forceinline__ float cl8(float x)  { return fminf(fmaxf(x, -8.f), 8.f); }

// LSTM activation for a float4 group
__device__ __forceinline__ void lstm_act4(const float* gi, const float* gf,
                                          const float* gg, const float* go,
                                          float* cv, float* hv) {
    float so[4], tc_d[4];
#pragma unroll
    for (int l = 0; l < 4; l++) {
        float di = 1.f + __expf(-cl16(gi[l]));
        float df = 1.f + __expf(-cl16(gf[l]));
        float dg = 1.f + __expf(-2.f * cl8(gg[l]));
        float dq = 1.f + __expf(-cl16(go[l]));
        float si, sf, rg, sq;
        rcp4(di, df, dg, dq, si, sf, rg, sq);
        float tg = 2.f * rg - 1.f;
        cv[l] = sf * cv[l] + si * tg;
        so[l] = sq;
        tc_d[l] = 1.f + __expf(-2.f * cl8(cv[l]));
    }
    float rc0, rc1, rc2, rc3;
    rcp4(tc_d[0], tc_d[1], tc_d[2], tc_d[3], rc0, rc1, rc2, rc3);
    hv[0] = so[0] * (2.f * rc0 - 1.f);
    hv[1] = so[1] * (2.f * rc1 - 1.f);
    hv[2] = so[2] * (2.f * rc2 - 1.f);
    hv[3] = so[3] * (2.f * rc3 - 1.f);
}

__device__ __forceinline__ void mma_f16(float& d0, float& d1, float& d2, float& d3,
                                        uint32_t a0, uint32_t a1, uint32_t a2, uint32_t a3,
                                        uint32_t b0, uint32_t b1) {
    asm volatile(
        "mma.sync.aligned.m16n8k16.row.col.f32.f16.f16.f32 "
        "{%0,%1,%2,%3}, {%4,%5,%6,%7}, {%8,%9}, {%0,%1,%2,%3};"
        : "+f"(d0), "+f"(d1), "+f"(d2), "+f"(d3)
        : "r"(a0), "r"(a1), "r"(a2), "r"(a3), "r"(b0), "r"(b1));
}

__device__ __forceinline__ void cpa16(uint32_t s, const void* g) {
    asm volatile("cp.async.cg.shared.global [%0], [%1], 16;" :: "r"(s), "l"(g));
}
#define CP_COMMIT() asm volatile("cp.async.commit_group;" ::: "memory")
#define CP_WAIT2()  asm volatile("cp.async.wait_group 2;" ::: "memory")

// ---------------- matrix pre-split into planar swizzled image ----------------
__device__ void split_weight(const float* __restrict__ W, int N, int lgK,
                             uint32_t* __restrict__ img, int gtid, int zrow) {
    const int K = 1 << lgK;
    const int KT = K >> 4;
    const int total = N << lgK;
    uint16_t* img16 = (uint16_t*)img;
    for (int e = gtid; e < total; e += GRIDB * NTHR) {
        int n = e >> lgK, k = e & (K - 1);
        int row = n & 127;
        int sw = ((row >> 2) & 1) << 2;
        int unit = (((k & 15) >> 1) ^ sw);
        size_t base = ((size_t)(n >> 7) * KT + (k >> 4)) * 4096;
        int idx = row * 16 + unit * 2 + (k & 1);
        float v = (n == zrow) ? 0.f : W[e];
        img16[base + idx]        = h0u(v);
        img16[base + 2048 + idx] = h1u(v);
    }
}

// ---------------- fp16 3-term MMA GEMM, planar frags, 4-stage cp.async ----------
__device__ void mma_gemm(uint32_t* sm,
    const uint32_t* __restrict__ A0, const uint32_t* __restrict__ W0,
    int ktB, int ktE, float* __restrict__ Cp, int ldc, int n0)
{
    const int tid  = threadIdx.x;
    const int warp = tid >> 5, lane = tid & 31;
    const int wm = warp >> 2, wn = warp & 3;       // 2 x 4 warp grid, warp tile 64x32
    const int gid = lane >> 2, cc = lane & 3;
    const int sw = (gid >= 4) ? 4 : 0;
    const int p0 = cc ^ sw, p1 = (cc ^ sw) ^ 4;
    const uint32_t sbase = (uint32_t)__cvta_generic_to_shared(sm);

    auto issue = [&](int kt, int stage) {
        const uint4* a4 = (const uint4*)(A0 + (size_t)kt * KTU);
        const uint4* w4 = (const uint4*)(W0 + (size_t)kt * KTU);
        uint32_t sa = sbase + stage * (STG_U * 4);
        uint32_t swp = sa + KTU * 4;
#pragma unroll
        for (int l = 0; l < 2; l++) {
            int s = tid + l * NTHR;
            cpa16(sa + s * 16, a4 + s);
            cpa16(swp + s * 16, w4 + s);
        }
    };

    float acc[4][4][4];
#pragma unroll
    for (int i = 0; i < 4; i++)
#pragma unroll
        for (int j = 0; j < 4; j++)
#pragma unroll
            for (int q = 0; q < 4; q++) acc[i][j][q] = 0.f;

    const int nkt = ktE - ktB;
#pragma unroll
    for (int s = 0; s < NSTG - 1; s++) {
        if (s < nkt) issue(ktB + s, s);
        CP_COMMIT();
    }

    for (int kt = ktB; kt < ktE; kt++) {
        CP_WAIT2();
        __syncthreads();   // stage kt ready AND all warps done with stage kt-1
        if (kt + NSTG - 1 < ktE) issue(kt + NSTG - 1, (kt - ktB + NSTG - 1) & (NSTG - 1));
        CP_COMMIT();

        const int st = (kt - ktB) & (NSTG - 1);
        const uint32_t* P0A = sm + st * STG_U;
        const uint32_t* P1A = P0A + 1024;
        const uint32_t* P0W = P0A + 2048;
        const uint32_t* P1W = P0A + 3072;

        uint32_t bs0[4][2], bs1[4][2];
#pragma unroll
        for (int nf = 0; nf < 4; nf++) {
            int n8 = (wn * 32 + nf * 8 + gid) * 8;
            bs0[nf][0] = P0W[n8 + p0];
            bs0[nf][1] = P0W[n8 + p1];
            bs1[nf][0] = P1W[n8 + p0];
            bs1[nf][1] = P1W[n8 + p1];
        }
#pragma unroll
        for (int mf = 0; mf < 4; mf++) {
            int m8a = (wm * 64 + mf * 16 + gid) * 8;
            int m8b = m8a + 64;
            uint32_t as0_0 = P0A[m8a + p0];
            uint32_t as0_1 = P0A[m8b + p0];
            uint32_t as0_2 = P0A[m8a + p1];
            uint32_t as0_3 = P0A[m8b + p1];
            uint32_t as1_0 = P1A[m8a + p0];
            uint32_t as1_1 = P1A[m8b + p0];
            uint32_t as1_2 = P1A[m8a + p1];
            uint32_t as1_3 = P1A[m8b + p1];
#pragma unroll
            for (int nf = 0; nf < 4; nf++) {
                float* d = acc[mf][nf];
                // 3-term: s0*s0 + s0*s1 + s1*s0 (dropped s1*s1 ~ 2^-22)
                mma_f16(d[0], d[1], d[2], d[3],
                        as0_0, as0_1, as0_2, as0_3, bs0[nf][0], bs0[nf][1]);
                mma_f16(d[0], d[1], d[2], d[3],
                        as0_0, as0_1, as0_2, as0_3, bs1[nf][0], bs1[nf][1]);
                mma_f16(d[0], d[1], d[2], d[3],
                        as1_0, as1_1, as1_2, as1_3, bs0[nf][0], bs0[nf][1]);
            }
        }
    }

#pragma unroll
    for (int mf = 0; mf < 4; mf++) {
        int m = wm * 64 + mf * 16 + gid;
#pragma unroll
        for (int nf = 0; nf < 4; nf++) {
            int col = n0 + wn * 32 + nf * 8 + 2 * cc;
            *(float2*)(Cp + (size_t)m * ldc + col) =
                make_float2(acc[mf][nf][0], acc[mf][nf][1]);
            *(float2*)(Cp + (size_t)(m + 8) * ldc + col) =
                make_float2(acc[mf][nf][2], acc[mf][nf][3]);
        }
    }
}

// ---------------- shared H-image writer ----------------
__device__ __forceinline__ void write_h(uint32_t* himg, int b, int j, const float* hv) {
    int p  = (j & 15) >> 1;
    int sb = ((b >> 2) & 1) << 2;
    uint32_t* P0 = himg + (size_t)(j >> 4) * KTU + b * 8;
    uint32_t* P1 = P0 + 1024;
    uint32_t l0 = (uint32_t)h0u(hv[0]) | ((uint32_t)h0u(hv[1]) << 16);
    uint32_t l1 = (uint32_t)h0u(hv[2]) | ((uint32_t)h0u(hv[3]) << 16);
    uint32_t r0 = (uint32_t)h1u(hv[0]) | ((uint32_t)h1u(hv[1]) << 16);
    uint32_t r1 = (uint32_t)h1u(hv[2]) | ((uint32_t)h1u(hv[3]) << 16);
    *(uint2*)&P0[p ^ sb] = make_uint2(l0, l1);
    *(uint2*)&P1[p ^ sb] = make_uint2(r0, r1);
}

// gate0 for ONE batch row b (block-local): sum Whh0 chunks [0..5] + EW0[tok] + bias
__device__ void gate0_row(const float* __restrict__ bias, float* __restrict__ c,
                          uint32_t* __restrict__ himg, int b, int tok, int tid)
{
    const float* er = g_EW0 + (size_t)tok * G4;
    const float* pb = g_part + (size_t)b * G4;
    for (int g = tid; g < Hid / 4; g += NTHR) {   // exactly 1 group per thread
        int j = g * 4;
        float4 gi = *(const float4*)&bias[j];
        float4 gf = *(const float4*)&bias[1024 + j];
        float4 gg = *(const float4*)&bias[2048 + j];
        float4 go = *(const float4*)&bias[3072 + j];
        {
            float4 a = *(const float4*)&er[j];
            float4 f = *(const float4*)&er[1024 + j];
            float4 gv = *(const float4*)&er[2048 + j];
            float4 o = *(const float4*)&er[3072 + j];
            gi.x += a.x; gi.y += a.y; gi.z += a.z; gi.w += a.w;
            gf.x += f.x; gf.y += f.y; gf.z += f.z; gf.w += f.w;
            gg.x += gv.x; gg.y += gv.y; gg.z += gv.z; gg.w += gv.w;
            go.x += o.x; go.y += o.y; go.z += o.z; go.w += o.w;
        }
#pragma unroll
        for (int ch = 0; ch < 6; ch++) {
            const float* q = pb + (size_t)ch * Bsz * G4;
            float4 a = *(const float4*)&q[j];
            float4 f = *(const float4*)&q[1024 + j];
            float4 gv = *(const float4*)&q[2048 + j];
            float4 o = *(const float4*)&q[3072 + j];
            gi.x += a.x; gi.y += a.y; gi.z += a.z; gi.w += a.w;
            gf.x += f.x; gf.y += f.y; gf.z += f.z; gf.w += f.w;
            gg.x += gv.x; gg.y += gv.y; gg.z += gv.z; gg.w += gv.w;
            go.x += o.x; go.y += o.y; go.z += o.z; go.w += o.w;
        }
        float cv[4], hv[4];
        *(float4*)cv = *(const float4*)&c[b * Hid + j];
        lstm_act4((const float*)&gi, (const float*)&gf,
                  (const float*)&gg, (const float*)&go, cv, hv);
        *(float4*)&c[b * Hid + j] = *(float4*)cv;
        write_h(himg, b, j, hv);
    }
}

// gate1: sum chunks [6..16]; write H1 image + C1 (grid-strided, all blocks)
__device__ void gate1_phase(const float* __restrict__ bias, float* __restrict__ c,
                            uint32_t* __restrict__ himg, int gtid)
{
    for (int g = gtid; g < (Bsz * Hid) / 4; g += GRIDB * NTHR) {
        int idx = g * 4;
        int b = idx >> 10, j = idx & 1023;
        float4 gi = *(const float4*)&bias[j];
        float4 gf = *(const float4*)&bias[1024 + j];
        float4 gg = *(const float4*)&bias[2048 + j];
        float4 go = *(const float4*)&bias[3072 + j];
        const float* pb = g_part + (size_t)b * G4;
#pragma unroll
        for (int ch = 6; ch < 17; ch++) {
            const float* q = pb + (size_t)ch * Bsz * G4;
            float4 a = *(const float4*)&q[j];
            float4 f = *(const float4*)&q[1024 + j];
            float4 gv = *(const float4*)&q[2048 + j];
            float4 o = *(const float4*)&q[3072 + j];
            gi.x += a.x; gi.y += a.y; gi.z += a.z; gi.w += a.w;
            gf.x += f.x; gf.y += f.y; gf.z += f.z; gf.w += f.w;
            gg.x += gv.x; gg.y += gv.y; gg.z += gv.z; gg.w += gv.w;
            go.x += o.x; go.y += o.y; go.z += o.z; go.w += o.w;
        }
        float cv[4], hv[4];
        *(float4*)cv = *(const float4*)&c[idx];
        lstm_act4((const float*)&gi, (const float*)&gf,
                  (const float*)&gg, (const float*)&go, cv, hv);
        *(float4*)&c[idx] = *(float4*)cv;
        write_h(himg, b, j, hv);
    }
}

// ---------------- params ----------------
struct Params {
    const int*   seq;
    const float* teacher_p;
    const float* embeds;
    const float* W_ih0; const float* W_hh0; const float* b_ih0; const float* b_hh0;
    const float* W_ih1; const float* W_hh1; const float* b_ih1; const float* b_hh1;
    const float* fc_w;  const float* fc_b;
    float* out;
};

// epilogue: sum logits partials, write out row `trow`, argmax; token for step
// `tsel` -> *s_tok (if tsel < Tlen). Ends with __syncthreads (reduction).
__device__ void epilogue(const Params& P, int trow, int tsel,
                         float* red_v, int* red_i, int* s_tok, int b, int tid)
{
    float* orow = P.out + ((size_t)b * Tlen + trow) * Vocab;
    float bv = -3.402823e38f; int bi = 0;
    for (int n4 = tid; n4 < Vocab / 4; n4 += NTHR) {
        int n = n4 * 4;
        float4 v = *(const float4*)&P.fc_b[n];
#pragma unroll
        for (int ch = 0; ch < LCH; ch++) {
            const float4 p4 = *(const float4*)
                &g_lpart[(size_t)ch * Bsz * Vocab + b * Vocab + n];
            v.x += p4.x; v.y += p4.y; v.z += p4.z; v.w += p4.w;
        }
        *(float4*)&orow[n] = v;
        if (v.x > bv) { bv = v.x; bi = n; }
        if (v.y > bv) { bv = v.y; bi = n + 1; }
        if (v.z > bv) { bv = v.z; bi = n + 2; }
        if (v.w > bv) { bv = v.w; bi = n + 3; }
    }
    red_v[tid] = bv; red_i[tid] = bi;
    __syncthreads();
    for (int s = NTHR / 2; s > 0; s >>= 1) {
        if (tid < s) {
            float v2 = red_v[tid + s]; int i2 = red_i[tid + s];
            if (v2 > red_v[tid] || (v2 == red_v[tid] && i2 < red_i[tid])) {
                red_v[tid] = v2; red_i[tid] = i2;
            }
        }
        __syncthreads();
    }
    if (tsel < Tlen && tid == 0) {
        bool teacher = g_dec[tsel * Bsz + b] != 0;
        *s_tok = teacher ? P.seq[b * Tlen + tsel] : red_i[0];
    }
}

// ---------------- the persistent kernel ----------------
__global__ void __launch_bounds__(NTHR, 2) lstm_persist(Params P)
{
    extern __shared__ uint32_t smem_dyn[];
    __shared__ float red_v[NTHR];
    __shared__ int   red_i[NTHR];
    __shared__ int   s_tok;

    const int tid  = threadIdx.x;
    const int blk  = blockIdx.x;
    const int gtid = blk * NTHR + tid;
    unsigned long long lgen = g_gen;   // generation continuation across graph replays

    // ================= setup =================
    for (int idx = gtid; idx < Bsz * Hid; idx += GRIDB * NTHR) {
        g_C0[idx] = 0.f; g_C1[idx] = 0.f;
    }
    for (int idx = gtid; idx < 64 * KTU; idx += GRIDB * NTHR) {
        g_H0i[idx] = 0u; g_H1i[idx] = 0u;
    }
    // zero partial chunks 0..5 (gate0 @ t=0) and 12..16 (gate1 @ t=0)
    for (int idx = gtid; idx < 6 * Bsz * G4; idx += GRIDB * NTHR)
        g_part[idx] = 0.f;
    for (int idx = gtid; idx < 5 * Bsz * G4; idx += GRIDB * NTHR)
        g_part[(size_t)12 * Bsz * G4 + idx] = 0.f;
    for (int i = gtid; i < G4; i += GRIDB * NTHR) {
        g_bias0[i] = P.b_ih0[i] + P.b_hh0[i];
        g_bias1[i] = P.b_ih1[i] + P.b_hh1[i];
    }
    if (gtid < Bsz) g_tok[gtid] = P.seq[gtid * Tlen];   // t=0 always teacher

    split_weight(P.W_ih0, G4,    9,  g_Wih0s, gtid, -1);
    split_weight(P.W_hh0, G4,    10, g_Whh0s, gtid, -1);
    split_weight(P.W_ih1, G4,    10, g_Wih1s, gtid, -1);
    split_weight(P.W_hh1, G4,    10, g_Whh1s, gtid, -1);
    split_weight(P.fc_w,  Vocab, 10, g_fcws,  gtid, -1);
    split_weight(P.embeds, Vocab, 9, g_Ei,    gtid, 0);   // zero padding row

    if (blk < 128) {
        // threefry-2x32, partitionable scheme: bits[i] = o0 ^ o1,
        // (o0,o1) = threefry2x32(key=(0,1), (hi32(i)=0, lo32(i)=i))
        int j = blk * NTHR + tid;
        const unsigned ks0 = 0u, ks1 = 1u, ks2 = 0u ^ 1u ^ 0x1BD11BDAu;
#pragma unroll
        for (int half = 0; half < 2; half++) {
            unsigned idx = (unsigned)j + (unsigned)half * 32768u;
            unsigned x0 = 0u, x1 = idx;
            x0 += ks0; x1 += ks1;
#define R4(a,b,c,d) \
            x0 += x1; x1 = rotl32(x1,a); x1 ^= x0; \
            x0 += x1; x1 = rotl32(x1,b); x1 ^= x0; \
            x0 += x1; x1 = rotl32(x1,c); x1 ^= x0; \
            x0 += x1; x1 = rotl32(x1,d); x1 ^= x0;
            R4(13,15,26,6);   x0 += ks1; x1 += ks2 + 1u;
            R4(17,29,16,24);  x0 += ks2; x1 += ks0 + 2u;
            R4(13,15,26,6);   x0 += ks0; x1 += ks1 + 3u;
            R4(17,29,16,24);  x0 += ks1; x1 += ks2 + 4u;
            R4(13,15,26,6);   x0 += ks2; x1 += ks0 + 5u;
#undef R4
            unsigned bits = x0 ^ x1;
            float p = *P.teacher_p;
            float u = __uint_as_float((bits >> 9) | 0x3f800000u) - 1.0f;
            g_dec[idx] = (u < p) ? 1 : 0;
        }
    }
    grid_sync(lgen);

    // ---- one-time: EW0 = emb @ Wih0^T (4 M-tiles x 32 N-tiles, full K=512) ----
    if (blk < 128) {
        int mt = blk >> 5, nt = blk & 31;
        mma_gemm(smem_dyn,
                 g_Ei + (size_t)mt * 32 * KTU, g_Wih0s + (size_t)nt * 32 * KTU,
                 0, 32, g_EW0 + (size_t)mt * 128 * G4, G4, nt * 128);
    }
    grid_sync(lgen);

    // ================= time loop (4 phases per step) =================
    for (int t = 0; t < Tlen; t++) {
        // PHA: blocks 0..127: epilogue(t-1) then gate0(t) for own batch row
        if (blk < 128) {
            if (t > 0) {
                epilogue(P, t - 1, t, red_v, red_i, &s_tok, blk, tid);
            } else if (tid == 0) {
                s_tok = g_tok[blk];
            }
            __syncthreads();
            gate0_row(g_bias0, g_C0, g_H0i, blk, s_tok, tid);
        }
        grid_sync(lgen);

        // PH3: Wih1@H0 -> chunks 6..11 (192 blks) | Whh0@H0 kt[0,32) -> 0..2 (96)
        if (blk < 192) {
            int tile = blk % 32, ch = blk / 32;        // 0..5
            int kb = ch * 64 / 6, ke = (ch + 1) * 64 / 6;
            mma_gemm(smem_dyn, g_H0i, g_Wih1s + (size_t)tile * 64 * KTU,
                     kb, ke, g_part + (size_t)(6 + ch) * Bsz * G4, G4, tile * 128);
        } else {
            int i = blk - 192, tile = i % 32, ch = i / 32;   // 0..2
            int kb = ch * 32 / 3, ke = (ch + 1) * 32 / 3;
            mma_gemm(smem_dyn, g_H0i, g_Whh0s + (size_t)tile * 64 * KTU,
                     kb, ke, g_part + (size_t)ch * Bsz * G4, G4, tile * 128);
        }
        grid_sync(lgen);

        // PH4: gate1(t) = chunks [6..16] + bias -> H1(t)
        gate1_phase(g_bias1, g_C1, g_H1i, gtid);
        grid_sync(lgen);

        // PH5: Whh1 -> 12..16 (160) | Whh0 kt[32,64) -> 3..5 (96) | logits (32)
        if (blk < 160) {
            int tile = blk % 32, ch = blk / 32;        // 0..4
            int kb = ch * 64 / 5, ke = (ch + 1) * 64 / 5;
            mma_gemm(smem_dyn, g_H1i, g_Whh1s + (size_t)tile * 64 * KTU,
                     kb, ke, g_part + (size_t)(12 + ch) * Bsz * G4, G4, tile * 128);
        } else if (blk < 256) {
            int i = blk - 160, tile = i % 32, ch = i / 32; // 0..2
            int kb = 32 + ch * 32 / 3, ke = 32 + (ch + 1) * 32 / 3;
            mma_gemm(smem_dyn, g_H0i, g_Whh0s + (size_t)tile * 64 * KTU,
                     kb, ke, g_part + (size_t)(3 + ch) * Bsz * G4, G4, tile * 128);
        } else {
            int i = blk - 256, nt = i & 3, ch = i >> 2;    // 0..7
            mma_gemm(smem_dyn, g_H1i, g_fcws + (size_t)nt * 64 * KTU,
                     ch * 8, ch * 8 + 8,
                     g_lpart + (size_t)ch * Bsz * Vocab, Vocab, nt * 128);
        }
        grid_sync(lgen);
    }

    // final epilogue: out row 511 (no next-token select)
    if (blk < 128)
        epilogue(P, Tlen - 1, Tlen, red_v, red_i, &s_tok, blk, tid);
}

// ---------------- host launch: ONE kernel node, fully graph-capturable ----------------
extern "C" void kernel_launch(void* const* d_in, const int* in_sizes, int n_in,
                              void* d_out, int out_size)
{
    Params P;
    P.seq       = (const int*)d_in[0];
    // d_in[1] = seq_lens (unused by the reference computation)
    P.teacher_p = (const float*)d_in[2];
    P.embeds    = (const float*)d_in[3];
    P.W_ih0     = (const float*)d_in[4];
    P.W_hh0     = (const float*)d_in[5];
    P.b_ih0     = (const float*)d_in[6];
    P.b_hh0     = (const float*)d_in[7];
    P.W_ih1     = (const float*)d_in[8];
    P.W_hh1     = (const float*)d_in[9];
    P.b_ih1     = (const float*)d_in[10];
    P.b_hh1     = (const float*)d_in[11];
    P.fc_w      = (const float*)d_in[12];
    P.fc_b      = (const float*)d_in[13];
    P.out       = (float*)d_out;

    cudaFuncSetAttribute(lstm_persist, cudaFuncAttributeMaxDynamicSharedMemorySize,
                         SMEM_DYN);
    lstm_persist<<<GRIDB, NTHR, SMEM_DYN>>>(P);
}